// round 3
// baseline (speedup 1.0000x reference)
#include <cuda_runtime.h>
#include <cuda_bf16.h>

#define N_NODES 100000
#define F 32

// Scratch (device globals; no allocation allowed in kernel_launch)
__device__ float g_dis[N_NODES];          // deg accumulator, then deg^{-1/2}
__device__ float g_aggX[N_NODES * 3];     // layer-1 aggregated raw features
__device__ float g_h1[N_NODES * F];       // layer-1 output (post relu)
__device__ float g_agg2[N_NODES * F];     // layer-2 aggregation buffer
__device__ float g_h2[N_NODES * F];       // layer-2 output (post relu)
__device__ float g_ypre[N_NODES];         // h2 @ W3 per node (scalar)

// ---------------------------------------------------------------------------
// init: deg starts at 1.0 (self loop); zero aggregation buffers
__global__ void init_kernel() {
    int i = blockIdx.x * blockDim.x + threadIdx.x;
    if (i < N_NODES * F) g_agg2[i] = 0.0f;
    if (i < N_NODES * 3) g_aggX[i] = 0.0f;
    if (i < N_NODES)     g_dis[i]  = 1.0f;
}

// deg[dst] += 1 per edge
__global__ void deg_kernel(const int* __restrict__ dst, int E) {
    int e = blockIdx.x * blockDim.x + threadIdx.x;
    if (e < E) atomicAdd(&g_dis[dst[e]], 1.0f);
}

// dis = rsqrt(deg)
__global__ void rsqrt_kernel() {
    int i = blockIdx.x * blockDim.x + threadIdx.x;
    if (i < N_NODES) g_dis[i] = rsqrtf(g_dis[i]);
}

// ---------------------------------------------------------------------------
// Layer 1 edge pass: aggregate raw x (3 features) — aggregation commutes with W1
__global__ void l1_edge(const int* __restrict__ src, const int* __restrict__ dst,
                        const float* __restrict__ x, int E) {
    int e = blockIdx.x * blockDim.x + threadIdx.x;
    if (e >= E) return;
    int s = __ldg(&src[e]);
    int d = __ldg(&dst[e]);
    float nrm = g_dis[s] * g_dis[d];
    atomicAdd(&g_aggX[d * 3 + 0], nrm * __ldg(&x[s * 3 + 0]));
    atomicAdd(&g_aggX[d * 3 + 1], nrm * __ldg(&x[s * 3 + 1]));
    atomicAdd(&g_aggX[d * 3 + 2], nrm * __ldg(&x[s * 3 + 2]));
}

// Layer 1 node pass: add self-loop term, matmul W1 (3x32), +b1, relu
// thread = (node, chunk of 4 outputs): 8 threads per node
__global__ void l1_node(const float* __restrict__ x,
                        const float* __restrict__ W1, const float* __restrict__ b1) {
    int t = blockIdx.x * blockDim.x + threadIdx.x;
    if (t >= N_NODES * 8) return;
    int n = t >> 3;
    int c = t & 7;
    float dis = g_dis[n];
    float d2 = dis * dis;
    float a0 = g_aggX[n * 3 + 0] + d2 * __ldg(&x[n * 3 + 0]);
    float a1 = g_aggX[n * 3 + 1] + d2 * __ldg(&x[n * 3 + 1]);
    float a2 = g_aggX[n * 3 + 2] + d2 * __ldg(&x[n * 3 + 2]);
    int f0 = c * 4;
    float4 o;
    o.x = fmaxf(0.0f, __ldg(&b1[f0 + 0]) + a0 * __ldg(&W1[0 * F + f0 + 0]) + a1 * __ldg(&W1[1 * F + f0 + 0]) + a2 * __ldg(&W1[2 * F + f0 + 0]));
    o.y = fmaxf(0.0f, __ldg(&b1[f0 + 1]) + a0 * __ldg(&W1[0 * F + f0 + 1]) + a1 * __ldg(&W1[1 * F + f0 + 1]) + a2 * __ldg(&W1[2 * F + f0 + 1]));
    o.z = fmaxf(0.0f, __ldg(&b1[f0 + 2]) + a0 * __ldg(&W1[0 * F + f0 + 2]) + a1 * __ldg(&W1[1 * F + f0 + 2]) + a2 * __ldg(&W1[2 * F + f0 + 2]));
    o.w = fmaxf(0.0f, __ldg(&b1[f0 + 3]) + a0 * __ldg(&W1[0 * F + f0 + 3]) + a1 * __ldg(&W1[1 * F + f0 + 3]) + a2 * __ldg(&W1[2 * F + f0 + 3]));
    *reinterpret_cast<float4*>(&g_h1[n * F + f0]) = o;
}

// ---------------------------------------------------------------------------
// Layer 2 edge pass: 8 threads per edge, each handles one float4 chunk of the
// 32-float row. Gather h1[src] (coalesced 128B row), scale, vector-red to agg2[dst].
__global__ void l2_edge(const int* __restrict__ src, const int* __restrict__ dst, int E) {
    long long t = (long long)blockIdx.x * blockDim.x + threadIdx.x;
    if (t >= (long long)E * 8) return;
    int e = (int)(t >> 3);
    int c = (int)(t & 7);
    int s = __ldg(&src[e]);
    int d = __ldg(&dst[e]);
    float nrm = g_dis[s] * g_dis[d];
    float4 v = __ldg(reinterpret_cast<const float4*>(&g_h1[s * F + c * 4]));
    v.x *= nrm; v.y *= nrm; v.z *= nrm; v.w *= nrm;
    float* p = &g_agg2[d * F + c * 4];
    asm volatile("red.global.add.v4.f32 [%0], {%1, %2, %3, %4};"
                 :: "l"(p), "f"(v.x), "f"(v.y), "f"(v.z), "f"(v.w) : "memory");
}

// Layer 2 node pass: self term + matmul W2 (32x32), +b2, relu
__global__ void l2_node(const float* __restrict__ W2, const float* __restrict__ b2) {
    int t = blockIdx.x * blockDim.x + threadIdx.x;
    if (t >= N_NODES * 8) return;
    int n = t >> 3;
    int c = t & 7;
    float dis = g_dis[n];
    float d2 = dis * dis;

    float in[F];
#pragma unroll
    for (int k4 = 0; k4 < 8; k4++) {
        float4 a = *reinterpret_cast<const float4*>(&g_agg2[n * F + k4 * 4]);
        float4 h = *reinterpret_cast<const float4*>(&g_h1[n * F + k4 * 4]);
        in[k4 * 4 + 0] = a.x + d2 * h.x;
        in[k4 * 4 + 1] = a.y + d2 * h.y;
        in[k4 * 4 + 2] = a.z + d2 * h.z;
        in[k4 * 4 + 3] = a.w + d2 * h.w;
    }
    int f0 = c * 4;
    float acc0 = __ldg(&b2[f0 + 0]);
    float acc1 = __ldg(&b2[f0 + 1]);
    float acc2 = __ldg(&b2[f0 + 2]);
    float acc3 = __ldg(&b2[f0 + 3]);
#pragma unroll
    for (int k = 0; k < F; k++) {
        float hv = in[k];
        acc0 += hv * __ldg(&W2[k * F + f0 + 0]);
        acc1 += hv * __ldg(&W2[k * F + f0 + 1]);
        acc2 += hv * __ldg(&W2[k * F + f0 + 2]);
        acc3 += hv * __ldg(&W2[k * F + f0 + 3]);
    }
    float4 o;
    o.x = fmaxf(0.0f, acc0);
    o.y = fmaxf(0.0f, acc1);
    o.z = fmaxf(0.0f, acc2);
    o.w = fmaxf(0.0f, acc3);
    *reinterpret_cast<float4*>(&g_h2[n * F + f0]) = o;
}

// ---------------------------------------------------------------------------
// Layer 3 node pass: y = h2 @ W3 (per node scalar); out[i] = b3 + dis^2 * y
__global__ void l3_node(const float* __restrict__ W3, const float* __restrict__ b3,
                        float* __restrict__ out) {
    int n = blockIdx.x * blockDim.x + threadIdx.x;
    if (n >= N_NODES) return;
    float y = 0.0f;
#pragma unroll
    for (int k4 = 0; k4 < 8; k4++) {
        float4 h = *reinterpret_cast<const float4*>(&g_h2[n * F + k4 * 4]);
        float4 w = __ldg(reinterpret_cast<const float4*>(&W3[k4 * 4]));
        y += h.x * w.x + h.y * w.y + h.z * w.z + h.w * w.w;
    }
    g_ypre[n] = y;
    float dis = g_dis[n];
    out[n] = __ldg(&b3[0]) + dis * dis * y;
}

// Layer 3 edge pass: scatter scalar messages
__global__ void l3_edge(const int* __restrict__ src, const int* __restrict__ dst,
                        float* __restrict__ out, int E) {
    int e = blockIdx.x * blockDim.x + threadIdx.x;
    if (e >= E) return;
    int s = __ldg(&src[e]);
    int d = __ldg(&dst[e]);
    atomicAdd(&out[d], g_dis[s] * g_dis[d] * g_ypre[s]);
}

// ---------------------------------------------------------------------------
extern "C" void kernel_launch(void* const* d_in, const int* in_sizes, int n_in,
                              void* d_out, int out_size) {
    const float* x  = (const float*)d_in[0];
    const int*   ei = (const int*)d_in[1];
    const float* W1 = (const float*)d_in[2];
    const float* b1 = (const float*)d_in[3];
    const float* W2 = (const float*)d_in[4];
    const float* b2 = (const float*)d_in[5];
    const float* W3 = (const float*)d_in[6];
    const float* b3 = (const float*)d_in[7];
    float* out = (float*)d_out;

    int E = in_sizes[1] / 2;
    const int* src = ei;
    const int* dst = ei + E;

    const int B = 256;
    init_kernel<<<(N_NODES * F + B - 1) / B, B>>>();
    deg_kernel<<<(E + B - 1) / B, B>>>(dst, E);
    rsqrt_kernel<<<(N_NODES + B - 1) / B, B>>>();

    l1_edge<<<(E + B - 1) / B, B>>>(src, dst, x, E);
    l1_node<<<(N_NODES * 8 + B - 1) / B, B>>>(x, W1, b1);

    long long t2 = (long long)E * 8;
    l2_edge<<<(unsigned)((t2 + B - 1) / B), B>>>(src, dst, E);
    l2_node<<<(N_NODES * 8 + B - 1) / B, B>>>(W2, b2);

    l3_node<<<(N_NODES + B - 1) / B, B>>>(W3, b3, out);
    l3_edge<<<(E + B - 1) / B, B>>>(src, dst, out, E);
}

// round 4
// speedup vs baseline: 1.4371x; 1.4371x over previous
#include <cuda_runtime.h>
#include <cuda_bf16.h>

#define N_NODES 100000
#define F 32

// Scratch (device globals)
__device__ float g_deg[N_NODES];            // degree (starts at 1 for self loop) -> dis
__device__ float g_dis[N_NODES];            // deg^{-1/2}
__device__ float4 g_x4[N_NODES];            // dis[n] * x[n], padded to 4 (w=0)
__device__ float4 g_agg1[N_NODES];          // layer-1 edge aggregation (float4)
__device__ float g_h1s[N_NODES * F];        // dis[n] * relu(layer1 out)
__device__ float g_agg2[N_NODES * F];       // layer-2 edge aggregation
__device__ float g_ys[N_NODES];             // dis[n] * (h2 @ W3)
__device__ float g_acc3[N_NODES];           // layer-3 edge aggregation

// ---------------------------------------------------------------------------
__global__ void init_kernel() {
    int i = blockIdx.x * blockDim.x + threadIdx.x;
    if (i < N_NODES * F) g_agg2[i] = 0.0f;
    if (i < N_NODES) {
        g_agg1[i] = make_float4(0.f, 0.f, 0.f, 0.f);
        g_acc3[i] = 0.0f;
        g_deg[i] = 1.0f;   // self loop
    }
}

__global__ void deg_kernel(const int* __restrict__ dst, int E) {
    int e = blockIdx.x * blockDim.x + threadIdx.x;
    if (e < E) atomicAdd(&g_deg[dst[e]], 1.0f);
}

// dis = rsqrt(deg); pre-scale x by dis (pad to float4)
__global__ void pre1_kernel(const float* __restrict__ x) {
    int n = blockIdx.x * blockDim.x + threadIdx.x;
    if (n >= N_NODES) return;
    float dis = rsqrtf(g_deg[n]);
    g_dis[n] = dis;
    float4 v;
    v.x = dis * __ldg(&x[n * 3 + 0]);
    v.y = dis * __ldg(&x[n * 3 + 1]);
    v.z = dis * __ldg(&x[n * 3 + 2]);
    v.w = 0.0f;
    g_x4[n] = v;
}

// ---------------------------------------------------------------------------
// Layer 1 edge pass: pure gather + vector RED (features pre-scaled by dis[src])
__global__ void l1_edge(const int* __restrict__ src, const int* __restrict__ dst, int E) {
    int e = blockIdx.x * blockDim.x + threadIdx.x;
    if (e >= E) return;
    int s = __ldg(&src[e]);
    int d = __ldg(&dst[e]);
    float4 v = __ldg(&g_x4[s]);
    float* p = reinterpret_cast<float*>(&g_agg1[d]);
    asm volatile("red.global.add.v4.f32 [%0], {%1, %2, %3, %4};"
                 :: "l"(p), "f"(v.x), "f"(v.y), "f"(v.z), "f"(v.w) : "memory");
}

// Layer 1 node pass: A = dis*(agg1 + x4_self); h1 = relu(A@W1+b1); store dis*h1
// 8 threads per node, each writes a float4 chunk of the 32-wide row.
__global__ void l1_node(const float* __restrict__ W1, const float* __restrict__ b1) {
    int t = blockIdx.x * blockDim.x + threadIdx.x;
    if (t >= N_NODES * 8) return;
    int n = t >> 3;
    int c = t & 7;
    float dis = g_dis[n];
    float4 a = g_agg1[n];
    float4 xs = g_x4[n];             // = dis*x  (self message scaled by dis[s]=dis[d])
    float a0 = dis * (a.x + xs.x);
    float a1 = dis * (a.y + xs.y);
    float a2 = dis * (a.z + xs.z);
    int f0 = c * 4;
    float4 o;
    o.x = dis * fmaxf(0.0f, __ldg(&b1[f0 + 0]) + a0 * __ldg(&W1[0 * F + f0 + 0]) + a1 * __ldg(&W1[1 * F + f0 + 0]) + a2 * __ldg(&W1[2 * F + f0 + 0]));
    o.y = dis * fmaxf(0.0f, __ldg(&b1[f0 + 1]) + a0 * __ldg(&W1[0 * F + f0 + 1]) + a1 * __ldg(&W1[1 * F + f0 + 1]) + a2 * __ldg(&W1[2 * F + f0 + 1]));
    o.z = dis * fmaxf(0.0f, __ldg(&b1[f0 + 2]) + a0 * __ldg(&W1[0 * F + f0 + 2]) + a1 * __ldg(&W1[1 * F + f0 + 2]) + a2 * __ldg(&W1[2 * F + f0 + 2]));
    o.w = dis * fmaxf(0.0f, __ldg(&b1[f0 + 3]) + a0 * __ldg(&W1[0 * F + f0 + 3]) + a1 * __ldg(&W1[1 * F + f0 + 3]) + a2 * __ldg(&W1[2 * F + f0 + 3]));
    *reinterpret_cast<float4*>(&g_h1s[n * F + f0]) = o;
}

// ---------------------------------------------------------------------------
// Layer 2 edge pass: 8 lanes per edge, each one float4 chunk; pure gather + RED.
__global__ void l2_edge(const int* __restrict__ src, const int* __restrict__ dst, int E) {
    long long t = (long long)blockIdx.x * blockDim.x + threadIdx.x;
    if (t >= (long long)E * 8) return;
    int e = (int)(t >> 3);
    int c = (int)(t & 7);
    int s = __ldg(&src[e]);
    int d = __ldg(&dst[e]);
    float4 v = __ldg(reinterpret_cast<const float4*>(&g_h1s[s * F + c * 4]));
    float* p = &g_agg2[d * F + c * 4];
    asm volatile("red.global.add.v4.f32 [%0], {%1, %2, %3, %4};"
                 :: "l"(p), "f"(v.x), "f"(v.y), "f"(v.z), "f"(v.w) : "memory");
}

// Layer 2+3 node pass (one warp per node):
//   in[k] = dis*(agg2[k] + h1s_self[k]);  h2[f] = relu(b2[f] + sum_k in[k]*W2[k,f])
//   y = sum_f h2[f]*W3[f];  store g_ys = dis*y
__global__ void l2l3_node(const float* __restrict__ W2, const float* __restrict__ b2,
                          const float* __restrict__ W3) {
    int gw = (blockIdx.x * blockDim.x + threadIdx.x) >> 5;  // global warp = node
    int lane = threadIdx.x & 31;
    if (gw >= N_NODES) return;
    int n = gw;
    float dis = g_dis[n];
    float inv = dis * (g_agg2[n * F + lane] + g_h1s[n * F + lane]);
    float acc = __ldg(&b2[lane]);
#pragma unroll
    for (int k = 0; k < F; k++) {
        float hv = __shfl_sync(0xFFFFFFFFu, inv, k);
        acc += hv * __ldg(&W2[k * F + lane]);
    }
    float h2 = fmaxf(0.0f, acc);
    float part = h2 * __ldg(&W3[lane]);
#pragma unroll
    for (int off = 16; off > 0; off >>= 1)
        part += __shfl_xor_sync(0xFFFFFFFFu, part, off);
    if (lane == 0) g_ys[n] = dis * part;
}

// Layer 3 edge pass: scalar gather + RED (no dis loads)
__global__ void l3_edge(const int* __restrict__ src, const int* __restrict__ dst, int E) {
    int e = blockIdx.x * blockDim.x + threadIdx.x;
    if (e >= E) return;
    int s = __ldg(&src[e]);
    int d = __ldg(&dst[e]);
    atomicAdd(&g_acc3[d], g_ys[s]);
}

// Finalize: out[n] = b3 + dis[n]*(acc3[n] + ys_self[n])
__global__ void finalize_kernel(const float* __restrict__ b3, float* __restrict__ out) {
    int n = blockIdx.x * blockDim.x + threadIdx.x;
    if (n >= N_NODES) return;
    out[n] = __ldg(&b3[0]) + g_dis[n] * (g_acc3[n] + g_ys[n]);
}

// ---------------------------------------------------------------------------
extern "C" void kernel_launch(void* const* d_in, const int* in_sizes, int n_in,
                              void* d_out, int out_size) {
    const float* x  = (const float*)d_in[0];
    const int*   ei = (const int*)d_in[1];
    const float* W1 = (const float*)d_in[2];
    const float* b1 = (const float*)d_in[3];
    const float* W2 = (const float*)d_in[4];
    const float* b2 = (const float*)d_in[5];
    const float* W3 = (const float*)d_in[6];
    const float* b3 = (const float*)d_in[7];
    float* out = (float*)d_out;

    int E = in_sizes[1] / 2;
    const int* src = ei;
    const int* dst = ei + E;

    const int B = 256;
    init_kernel<<<(N_NODES * F + B - 1) / B, B>>>();
    deg_kernel<<<(E + B - 1) / B, B>>>(dst, E);
    pre1_kernel<<<(N_NODES + B - 1) / B, B>>>(x);

    l1_edge<<<(E + B - 1) / B, B>>>(src, dst, E);
    l1_node<<<(N_NODES * 8 + B - 1) / B, B>>>(W1, b1);

    long long t2 = (long long)E * 8;
    l2_edge<<<(unsigned)((t2 + B - 1) / B), B>>>(src, dst, E);
    l2l3_node<<<(N_NODES * 32 + B - 1) / B, B>>>(W2, b2, W3);

    l3_edge<<<(E + B - 1) / B, B>>>(src, dst, E);
    finalize_kernel<<<(N_NODES + B - 1) / B, B>>>(b3, out);
}